// round 17
// baseline (speedup 1.0000x reference)
#include <cuda_runtime.h>
#include <cuda_bf16.h>
#include <math.h>
#include <cstdint>

#define BSZ 2048
#define NFIELD 100
#define NEMB 64
#define NHID 256
#define MLPH 1024
#define KDIM (NHID*NEMB)   // 16384
#define K3 (3*KDIM)        // 49152
#define KG 192             // gates GEMM K (3*64)
#define MFLAT (BSZ*NFIELD) // 204800

typedef unsigned long long ull;

// ---------------- scratch ----------------
__device__ float g_arm[(size_t)BSZ*NHID*NEMB];
__device__ double2 g_part[(size_t)BSZ*NHID];
__device__ float g_z0[(size_t)BSZ*MLPH];
__device__ float g_z1[(size_t)BSZ*MLPH];
__device__ float g_s0[NHID],  g_t0[NHID];
__device__ float g_s1[MLPH],  g_t1[MLPH];
__device__ float g_s2[MLPH],  g_t2[MLPH];
__device__ __nv_bfloat16 g_a3[(size_t)BSZ*K3];
__device__ __nv_bfloat16 g_b3[(size_t)MLPH*K3];
// front pipeline
__device__ float g_emb[(size_t)BSZ*NFIELD*NEMB];        // gathered+scaled emb
__device__ __nv_bfloat16 g_k3[(size_t)MFLAT*KG];        // keys split [kh|kh|kl]
__device__ __nv_bfloat16 g_q3[(size_t)NHID*KG];         // query split [qh|ql|qh]
__device__ float g_gates[(size_t)MFLAT*NHID];           // gates [b*100+f][o]

// ---------------- helpers ----------------
__device__ __forceinline__ ull pack2(float x, float y) {
    ull r;
    asm("mov.b64 %0, {%1, %2};" : "=l"(r) : "r"(__float_as_uint(x)), "r"(__float_as_uint(y)));
    return r;
}
__device__ __forceinline__ void unpack2(ull v, float& x, float& y) {
    unsigned lo, hi;
    asm("mov.b64 {%0, %1}, %2;" : "=r"(lo), "=r"(hi) : "l"(v));
    x = __uint_as_float(lo); y = __uint_as_float(hi);
}
__device__ __forceinline__ void fma2(ull& d, ull a, ull b) {
    asm("fma.rn.f32x2 %0, %1, %2, %0;" : "+l"(d) : "l"(a), "l"(b));
}
__device__ __forceinline__ float exp_cr(float x) {
    double xd = (double)x;
    if (fabsf(x) < 5e-4f) {
        return (float)(1.0 + xd*(1.0 + xd*(0.5 + xd*(1.0/6.0))));
    }
    return (float)exp(xd);
}
__device__ __forceinline__ uint32_t smem_u32(const void* p) {
    uint32_t a;
    asm("{ .reg .u64 t; cvta.to.shared.u64 t, %1; cvt.u32.u64 %0, t; }" : "=r"(a) : "l"(p));
    return a;
}
__device__ __forceinline__ void ldsm_x4(uint32_t* r, uint32_t addr) {
    asm volatile("ldmatrix.sync.aligned.m8n8.x4.shared.b16 {%0,%1,%2,%3}, [%4];"
        : "=r"(r[0]), "=r"(r[1]), "=r"(r[2]), "=r"(r[3]) : "r"(addr));
}
__device__ __forceinline__ void mma_bf16(float* c, const uint32_t* a, uint32_t b0, uint32_t b1) {
    asm volatile("mma.sync.aligned.m16n8k16.row.col.f32.bf16.bf16.f32 "
        "{%0,%1,%2,%3}, {%4,%5,%6,%7}, {%8,%9}, {%0,%1,%2,%3};"
        : "+f"(c[0]), "+f"(c[1]), "+f"(c[2]), "+f"(c[3])
        : "r"(a[0]), "r"(a[1]), "r"(a[2]), "r"(a[3]), "r"(b0), "r"(b1));
}

// ---------------- embkeys: gather emb, compute keys, write splits ----------------
#define EK_SMEM ((6400 + 64*66) * 4)
__global__ __launch_bounds__(256) void embkeys_kernel(
    const int* __restrict__ ids, const float* __restrict__ values,
    const float* __restrict__ emb_table, const float* __restrict__ wb)
{
    extern __shared__ float sm[];
    float* emb_s = sm;
    float* wb_s  = sm + 6400;
    const int b = blockIdx.x, t = threadIdx.x;

    for (int i = t; i < 64*64; i += 256) {
        int k = i >> 6, e = i & 63;
        wb_s[k*66 + e] = wb[i];
    }
    for (int i = t; i < NFIELD*64; i += 256) {
        int f = i >> 6, e = i & 63;
        int id = ids[b*NFIELD + f];
        float v = values[b*NFIELD + f];
        v = fminf(fmaxf(v, 0.001f), 1.0f);
        emb_s[i] = emb_table[(size_t)id*64 + e] * v;
    }
    __syncthreads();

    {
        float4* dst = (float4*)(g_emb + (size_t)b*NFIELD*64);
        const float4* src = (const float4*)emb_s;
        for (int i = t; i < NFIELD*16; i += 256) dst[i] = src[i];
    }

    for (int i = t; i < NFIELD*64; i += 256) {
        int f = i >> 6, k = i & 63;
        const ull* er = (const ull*)(emb_s + f*64);
        const ull* wr = (const ull*)(wb_s  + k*66);
        ull a0=0, a1=0, a2v=0, a3=0;
        #pragma unroll
        for (int e = 0; e < 32; e += 4) {
            fma2(a0,  er[e+0], wr[e+0]);
            fma2(a1,  er[e+1], wr[e+1]);
            fma2(a2v, er[e+2], wr[e+2]);
            fma2(a3,  er[e+3], wr[e+3]);
        }
        float x0,x1,x2,x3,x4,x5,x6,x7;
        unpack2(a0,x0,x1); unpack2(a1,x2,x3); unpack2(a2v,x4,x5); unpack2(a3,x6,x7);
        float key = ((x0+x1)+(x2+x3)) + ((x4+x5)+(x6+x7));
        __nv_bfloat16 kh = __float2bfloat16(key);
        __nv_bfloat16 kl = __float2bfloat16(key - __bfloat162float(kh));
        __nv_bfloat16* row = g_k3 + ((size_t)b*NFIELD + f)*KG;
        row[k]       = kh;
        row[64 + k]  = kh;
        row[128 + k] = kl;
    }
}

// ---------------- convQ: query [256,64] -> q3 [256,192] = [qh|ql|qh] ----------------
__global__ void convQ_kernel(const float* __restrict__ query)
{
    const int o = threadIdx.x;
    for (int k = 0; k < 64; k++) {
        float q = query[o*64 + k];
        __nv_bfloat16 qh = __float2bfloat16(q);
        __nv_bfloat16 ql = __float2bfloat16(q - __bfloat162float(qh));
        __nv_bfloat16* row = g_q3 + (size_t)o*KG;
        row[k]       = qh;
        row[64 + k]  = ql;
        row[128 + k] = qh;
    }
}

// ---------------- gates GEMM: g_gates = k3 @ q3^T * 0.0625 ----------------
#define GG_ROWP 72
#define GG_ASZ (128*GG_ROWP)
#define GG_SMEM (4*GG_ASZ*2)
#define GG_NIT (KG/64)   // 3
__global__ __launch_bounds__(256) void gates_gemm()
{
    extern __shared__ __nv_bfloat16 smb[];
    const int t = threadIdx.x, lane = t & 31, wid = t >> 5;
    const int wm = wid & 3, wn = wid >> 2;
    const int n0 = blockIdx.x << 7, m0 = blockIdx.y << 7;

    const __nv_bfloat16* Ag = g_k3 + (size_t)m0 * KG;
    const __nv_bfloat16* Bg = g_q3 + (size_t)n0 * KG;

    int crow[4], ccol[4];
    #pragma unroll
    for (int j = 0; j < 4; j++) {
        int c = j*256 + t;
        crow[j] = c >> 3;
        ccol[j] = (c & 7) * 8;
    }
    float acc[2][8][4];
    #pragma unroll
    for (int i = 0; i < 2; i++)
        #pragma unroll
        for (int jj = 0; jj < 8; jj++)
            #pragma unroll
            for (int q = 0; q < 4; q++) acc[i][jj][q] = 0.f;

    __nv_bfloat16* sA0 = smb;
    __nv_bfloat16* sA1 = smb + GG_ASZ;
    __nv_bfloat16* sB0 = smb + 2*GG_ASZ;
    __nv_bfloat16* sB1 = smb + 3*GG_ASZ;
    const uint32_t sb32 = smem_u32(smb);

    #pragma unroll
    for (int j = 0; j < 4; j++) {
        *(uint4*)(sA0 + crow[j]*GG_ROWP + ccol[j]) =
            *(const uint4*)(Ag + (size_t)crow[j]*KG + ccol[j]);
        *(uint4*)(sB0 + crow[j]*GG_ROWP + ccol[j]) =
            *(const uint4*)(Bg + (size_t)crow[j]*KG + ccol[j]);
    }
    __syncthreads();

    const int arowl = wm*32 + (lane & 15);
    const int akof  = (lane >> 4) * 8;
    const int browl = wn*64 + ((lane >> 4) & 1)*8 + (lane & 7);
    const int bkof  = ((lane >> 3) & 1) * 8;

    for (int it = 0; it < GG_NIT; it++) {
        const int buf = it & 1;
        uint4 ra[4], rb[4];
        if (it + 1 < GG_NIT) {
            const int kn = (it + 1) << 6;
            #pragma unroll
            for (int j = 0; j < 4; j++) {
                ra[j] = *(const uint4*)(Ag + (size_t)crow[j]*KG + kn + ccol[j]);
                rb[j] = *(const uint4*)(Bg + (size_t)crow[j]*KG + kn + ccol[j]);
            }
        }
        const uint32_t sA = sb32 + (buf ? GG_ASZ*2 : 0);
        const uint32_t sB = sb32 + (buf ? 3*GG_ASZ*2 : 2*GG_ASZ*2);
        #pragma unroll
        for (int kk = 0; kk < 4; kk++) {
            uint32_t af[2][4], bfr[4][4];
            #pragma unroll
            for (int tim = 0; tim < 2; tim++)
                ldsm_x4(af[tim], sA + (uint32_t)(((arowl + tim*16)*GG_ROWP + kk*16 + akof) * 2));
            #pragma unroll
            for (int g = 0; g < 4; g++)
                ldsm_x4(bfr[g], sB + (uint32_t)(((browl + g*16)*GG_ROWP + kk*16 + bkof) * 2));
            #pragma unroll
            for (int tim = 0; tim < 2; tim++)
                #pragma unroll
                for (int tin = 0; tin < 8; tin++) {
                    const int g = tin >> 1, sub = tin & 1;
                    mma_bf16(acc[tim][tin], af[tim], bfr[g][sub*2], bfr[g][sub*2+1]);
                }
        }
        if (it + 1 < GG_NIT) {
            __nv_bfloat16* dA = buf ? sA0 : sA1;
            __nv_bfloat16* dB = buf ? sB0 : sB1;
            #pragma unroll
            for (int j = 0; j < 4; j++) {
                *(uint4*)(dA + crow[j]*GG_ROWP + ccol[j]) = ra[j];
                *(uint4*)(dB + crow[j]*GG_ROWP + ccol[j]) = rb[j];
            }
        }
        __syncthreads();
    }

    #pragma unroll
    for (int tim = 0; tim < 2; tim++)
        #pragma unroll
        for (int tin = 0; tin < 8; tin++) {
            int m = m0 + wm*32 + tim*16 + (lane >> 2);
            int n = n0 + wn*64 + tin*8 + (lane & 3)*2;
            g_gates[(size_t)m*NHID + n]       = acc[tim][tin][0] * 0.0625f;
            g_gates[(size_t)m*NHID + n + 1]   = acc[tim][tin][1] * 0.0625f;
            g_gates[(size_t)(m+8)*NHID + n]   = acc[tim][tin][2] * 0.0625f;
            g_gates[(size_t)(m+8)*NHID + n+1] = acc[tim][tin][3] * 0.0625f;
        }
}

// ---------------- front_v4: bisection + arm from precomputed gates ----------------
#define FV_SMEM ((6400 + 100*257) * 4)
__global__ __launch_bounds__(256) void front_v4(const float* __restrict__ attv)
{
    extern __shared__ float sm[];
    float* emb_s  = sm;
    float* gstage = sm + 6400;
    const int b = blockIdx.x, t = threadIdx.x;

    {
        float4* de = (float4*)emb_s;
        const float4* se = (const float4*)(g_emb + (size_t)b*NFIELD*64);
        for (int i = t; i < NFIELD*16; i += 256) de[i] = se[i];
        const float* gg = g_gates + (size_t)b*NFIELD*NHID;
        for (int i = t; i < NFIELD*NHID; i += 256) {
            int f = i >> 8, o = i & 255;
            gstage[f*257 + o] = gg[i];
        }
    }
    __syncthreads();

    const int o = t;
    float r[NFIELD];
    float mx = -1e30f;
    #pragma unroll
    for (int f = 0; f < NFIELD; f++) {
        float x = gstage[f*257 + o];
        r[f] = x;
        mx = fmaxf(mx, x);
    }

    float tau = mx - 1.0f;
    float dm  = (mx - 0.1f) - tau;
    #pragma unroll 1
    for (int it = 0; it < 30; it++) {
        dm *= 0.5f;
        float tm = tau + dm;
        float s0 = 0.f, s1 = 0.f;
        #pragma unroll
        for (int f = 0; f < NFIELD; f += 2) {
            float d0 = fmaxf(r[f]   - tm, 0.f);
            float d1 = fmaxf(r[f+1] - tm, 0.f);
            s0 = fmaf(d0, d0, s0);
            s1 = fmaf(d1, d1, s1);
        }
        if (s0 + s1 >= 1.0f) tau = tm;
    }
    float psum = 0.f;
    #pragma unroll
    for (int f = 0; f < NFIELD; f++) {
        float d = fmaxf(r[f] - tau, 0.f);
        float p = d * d;
        r[f] = p;
        psum += p;
    }
    float inv = 1.0f / psum;
    const float* ar = attv + o*NFIELD;
    #pragma unroll
    for (int f = 0; f < NFIELD; f++) r[f] *= inv * ar[f];

    float2* outp = (float2*)(g_arm + ((size_t)b*NHID + o)*NEMB);
    double s = 0.0, s2 = 0.0;
    #pragma unroll
    for (int half = 0; half < 2; half++) {
        ull acc[16];
        #pragma unroll
        for (int j = 0; j < 16; j++) acc[j] = 0ull;
        #pragma unroll
        for (int f = 0; f < NFIELD; f++) {
            float w = r[f];
            ull w2 = pack2(w, w);
            const ull* er = (const ull*)(emb_s + f*64) + half*16;
            #pragma unroll
            for (int j = 0; j < 16; j++) fma2(acc[j], w2, er[j]);
        }
        #pragma unroll
        for (int j = 0; j < 16; j++) {
            float lo, hi; unpack2(acc[j], lo, hi);
            float elo = exp_cr(lo), ehi = exp_cr(hi);
            s += elo; s2 += (double)elo * (double)elo;
            s += ehi; s2 += (double)ehi * (double)ehi;
            outp[half*16 + j] = make_float2(elo, ehi);
        }
    }
    g_part[(size_t)b*NHID + o] = make_double2(s, s2);
}

// ---------------- BN stats ----------------
__global__ void stats_arm_kernel(const float* __restrict__ gamma,
                                 const float* __restrict__ beta)
{
    const int o = blockIdx.x, t = threadIdx.x;
    double s = 0.0, s2 = 0.0;
    for (int bb = t; bb < BSZ; bb += 256) {
        double2 p = g_part[(size_t)bb*NHID + o];
        s += p.x; s2 += p.y;
    }
    __shared__ double sh_[512];
    sh_[t] = s; sh_[256+t] = s2; __syncthreads();
    for (int st = 128; st > 0; st >>= 1) {
        if (t < st) { sh_[t] += sh_[t+st]; sh_[256+t] += sh_[256+t+st]; }
        __syncthreads();
    }
    if (t == 0) {
        double n = (double)BSZ * NEMB;
        double mean = sh_[0] / n;
        double var  = sh_[256] / n - mean*mean;
        double scl  = (double)gamma[o] / sqrt(var + 1e-5);
        g_s0[o] = (float)scl;
        g_t0[o] = (float)((double)beta[o] - mean*scl);
    }
}

__global__ void stats_z_kernel(const float* __restrict__ z,
                               const float* __restrict__ gamma,
                               const float* __restrict__ beta, int sel)
{
    const int n = blockIdx.x, t = threadIdx.x;
    double s = 0.0, s2 = 0.0;
    for (int bb = t; bb < BSZ; bb += 256) {
        float v = z[(size_t)bb*MLPH + n];
        s += v; s2 += (double)v * (double)v;
    }
    __shared__ double sh_[512];
    sh_[t] = s; sh_[256+t] = s2; __syncthreads();
    for (int st = 128; st > 0; st >>= 1) {
        if (t < st) { sh_[t] += sh_[t+st]; sh_[256+t] += sh_[256+t+st]; }
        __syncthreads();
    }
    if (t == 0) {
        double mean = sh_[0] / BSZ;
        double var  = sh_[256] / BSZ - mean*mean;
        double scl  = (double)gamma[n] / sqrt(var + 1e-5);
        if (sel == 1) { g_s1[n] = (float)scl; g_t1[n] = (float)((double)beta[n] - mean*scl); }
        else          { g_s2[n] = (float)scl; g_t2[n] = (float)((double)beta[n] - mean*scl); }
    }
}

// ---------------- triple-K split conversion ----------------
__global__ __launch_bounds__(256) void convA_kernel()
{
    size_t i = ((size_t)blockIdx.x*256 + threadIdx.x) * 4;
    float4 a = *(const float4*)(g_arm + i);
    int k = (int)(i & (KDIM-1));
    size_t m = i >> 14;
    int oo = k >> 6;
    float s = g_s0[oo], h = g_t0[oo];
    float v0 = fmaf(a.x,s,h), v1 = fmaf(a.y,s,h), v2 = fmaf(a.z,s,h), v3 = fmaf(a.w,s,h);
    __nv_bfloat16 h0 = __float2bfloat16(v0), h1 = __float2bfloat16(v1);
    __nv_bfloat16 h2 = __float2bfloat16(v2), h3 = __float2bfloat16(v3);
    __nv_bfloat16 l0 = __float2bfloat16(v0 - __bfloat162float(h0));
    __nv_bfloat16 l1 = __float2bfloat16(v1 - __bfloat162float(h1));
    __nv_bfloat16 l2 = __float2bfloat16(v2 - __bfloat162float(h2));
    __nv_bfloat16 l3 = __float2bfloat16(v3 - __bfloat162float(h3));
    __nv_bfloat16* base = g_a3 + m*K3 + k;
    *(__nv_bfloat162*)(base)               = __nv_bfloat162(h0, h1);
    *(__nv_bfloat162*)(base + 2)           = __nv_bfloat162(h2, h3);
    *(__nv_bfloat162*)(base + KDIM)        = __nv_bfloat162(h0, h1);
    *(__nv_bfloat162*)(base + KDIM + 2)    = __nv_bfloat162(h2, h3);
    *(__nv_bfloat162*)(base + 2*KDIM)      = __nv_bfloat162(l0, l1);
    *(__nv_bfloat162*)(base + 2*KDIM + 2)  = __nv_bfloat162(l2, l3);
}

__global__ __launch_bounds__(256) void convB_kernel(const float* __restrict__ W, int blk0)
{
    size_t i = ((size_t)(blockIdx.x + blk0)*256 + threadIdx.x) * 4;
    float4 a = *(const float4*)(W + i);
    int k = (int)(i & (KDIM-1));
    size_t n = i >> 14;
    __nv_bfloat16 h0 = __float2bfloat16(a.x), h1 = __float2bfloat16(a.y);
    __nv_bfloat16 h2 = __float2bfloat16(a.z), h3 = __float2bfloat16(a.w);
    __nv_bfloat16 l0 = __float2bfloat16(a.x - __bfloat162float(h0));
    __nv_bfloat16 l1 = __float2bfloat16(a.y - __bfloat162float(h1));
    __nv_bfloat16 l2 = __float2bfloat16(a.z - __bfloat162float(h2));
    __nv_bfloat16 l3 = __float2bfloat16(a.w - __bfloat162float(h3));
    __nv_bfloat16* base = g_b3 + n*K3 + k;
    *(__nv_bfloat162*)(base)               = __nv_bfloat162(h0, h1);
    *(__nv_bfloat162*)(base + 2)           = __nv_bfloat162(h2, h3);
    *(__nv_bfloat162*)(base + KDIM)        = __nv_bfloat162(l0, l1);
    *(__nv_bfloat162*)(base + KDIM + 2)    = __nv_bfloat162(l2, l3);
    *(__nv_bfloat162*)(base + 2*KDIM)      = __nv_bfloat162(h0, h1);
    *(__nv_bfloat162*)(base + 2*KDIM + 2)  = __nv_bfloat162(h2, h3);
}

// ---------------- HMMA GEMM0 ----------------
#define G0_ROWP 72
#define G0_ASZ (128*G0_ROWP)
#define G0_SMEM_BYTES (4*G0_ASZ*2)
#define G0_NIT (K3/64)

__global__ __launch_bounds__(256) void gemm0_mma(const float* __restrict__ bias,
                                                 float* __restrict__ C)
{
    extern __shared__ __nv_bfloat16 smb[];
    const int t = threadIdx.x, lane = t & 31, wid = t >> 5;
    const int wm = wid & 3, wn = wid >> 2;
    const int n0 = blockIdx.x << 7, m0 = blockIdx.y << 7;

    const __nv_bfloat16* Ag = g_a3 + (size_t)m0 * K3;
    const __nv_bfloat16* Bg = g_b3 + (size_t)n0 * K3;

    int crow[4], ccol[4];
    #pragma unroll
    for (int j = 0; j < 4; j++) {
        int c = j*256 + t;
        crow[j] = c >> 3;
        ccol[j] = (c & 7) * 8;
    }
    float acc[2][8][4];
    #pragma unroll
    for (int i = 0; i < 2; i++)
        #pragma unroll
        for (int jj = 0; jj < 8; jj++)
            #pragma unroll
            for (int q = 0; q < 4; q++) acc[i][jj][q] = 0.f;

    __nv_bfloat16* sA0 = smb;
    __nv_bfloat16* sA1 = smb + G0_ASZ;
    __nv_bfloat16* sB0 = smb + 2*G0_ASZ;
    __nv_bfloat16* sB1 = smb + 3*G0_ASZ;
    const uint32_t sb32 = smem_u32(smb);

    #pragma unroll
    for (int j = 0; j < 4; j++) {
        *(uint4*)(sA0 + crow[j]*G0_ROWP + ccol[j]) =
            *(const uint4*)(Ag + (size_t)crow[j]*K3 + ccol[j]);
        *(uint4*)(sB0 + crow[j]*G0_ROWP + ccol[j]) =
            *(const uint4*)(Bg + (size_t)crow[j]*K3 + ccol[j]);
    }
    __syncthreads();

    const int arowl = wm*32 + (lane & 15);
    const int akof  = (lane >> 4) * 8;
    const int browl = wn*64 + ((lane >> 4) & 1)*8 + (lane & 7);
    const int bkof  = ((lane >> 3) & 1) * 8;

    for (int it = 0; it < G0_NIT; it++) {
        const int buf = it & 1;
        uint4 ra[4], rb[4];
        if (it + 1 < G0_NIT) {
            const int kn = (it + 1) << 6;
            #pragma unroll
            for (int j = 0; j < 4; j++) {
                ra[j] = *(const uint4*)(Ag + (size_t)crow[j]*K3 + kn + ccol[j]);
                rb[j] = *(const uint4*)(Bg + (size_t)crow[j]*K3 + kn + ccol[j]);
            }
        }
        const uint32_t sA = sb32 + (buf ? G0_ASZ*2 : 0);
        const uint32_t sB = sb32 + (buf ? 3*G0_ASZ*2 : 2*G0_ASZ*2);
        #pragma unroll
        for (int kk = 0; kk < 4; kk++) {
            uint32_t af[2][4], bfr[4][4];
            #pragma unroll
            for (int tim = 0; tim < 2; tim++)
                ldsm_x4(af[tim], sA + (uint32_t)(((arowl + tim*16)*G0_ROWP + kk*16 + akof) * 2));
            #pragma unroll
            for (int g = 0; g < 4; g++)
                ldsm_x4(bfr[g], sB + (uint32_t)(((browl + g*16)*G0_ROWP + kk*16 + bkof) * 2));
            #pragma unroll
            for (int tim = 0; tim < 2; tim++)
                #pragma unroll
                for (int tin = 0; tin < 8; tin++) {
                    const int g = tin >> 1, sub = tin & 1;
                    mma_bf16(acc[tim][tin], af[tim], bfr[g][sub*2], bfr[g][sub*2+1]);
                }
        }
        if (it + 1 < G0_NIT) {
            __nv_bfloat16* dA = buf ? sA0 : sA1;
            __nv_bfloat16* dB = buf ? sB0 : sB1;
            #pragma unroll
            for (int j = 0; j < 4; j++) {
                *(uint4*)(dA + crow[j]*G0_ROWP + ccol[j]) = ra[j];
                *(uint4*)(dB + crow[j]*G0_ROWP + ccol[j]) = rb[j];
            }
        }
        __syncthreads();
    }

    #pragma unroll
    for (int tim = 0; tim < 2; tim++)
        #pragma unroll
        for (int tin = 0; tin < 8; tin++) {
            int m = m0 + wm*32 + tim*16 + (lane >> 2);
            int n = n0 + wn*64 + tin*8 + (lane & 3)*2;
            float b0v = bias[n], b1v = bias[n+1];
            C[(size_t)m*MLPH + n]       = acc[tim][tin][0] + b0v;
            C[(size_t)m*MLPH + n + 1]   = acc[tim][tin][1] + b1v;
            C[(size_t)(m+8)*MLPH + n]   = acc[tim][tin][2] + b0v;
            C[(size_t)(m+8)*MLPH + n+1] = acc[tim][tin][3] + b1v;
        }
}

// ---------------- SIMT GEMM for MLP1 ----------------
__global__ __launch_bounds__(256) void gemm_bn1(
    const float* __restrict__ A, const float* __restrict__ B,
    const float* __restrict__ bias, float* __restrict__ C,
    int M, int N, int K)
{
    __shared__ float As[16][132];
    __shared__ float Bs[16][132];
    const int t  = threadIdx.x;
    const int tx = t & 15, ty = t >> 4;
    const int m0 = blockIdx.y << 7, n0 = blockIdx.x << 7;
    const int lr = t >> 2;
    const int lc = (t & 3) << 2;

    const float* Ap0 = A + (size_t)(m0 + lr) * K + lc;
    const float* Ap1 = Ap0 + (size_t)64 * K;
    const float* Bp0 = B + (size_t)(n0 + lr) * K + lc;
    const float* Bp1 = Bp0 + (size_t)64 * K;

    float4 ra0 = *(const float4*)Ap0;
    float4 ra1 = *(const float4*)Ap1;
    float4 rb0 = *(const float4*)Bp0;
    float4 rb1 = *(const float4*)Bp1;

    ull acc[8][4];
    #pragma unroll
    for (int i = 0; i < 8; i++)
        #pragma unroll
        for (int j = 0; j < 4; j++) acc[i][j] = 0ull;

    for (int k0 = 0; k0 < K; k0 += 16) {
        float4 ta0 = ra0, ta1 = ra1;
        float4 sv = *(const float4*)(g_s1 + k0 + lc);
        float4 hv = *(const float4*)(g_t1 + k0 + lc);
        ta0.x=fmaxf(fmaf(ta0.x,sv.x,hv.x),0.f); ta0.y=fmaxf(fmaf(ta0.y,sv.y,hv.y),0.f);
        ta0.z=fmaxf(fmaf(ta0.z,sv.z,hv.z),0.f); ta0.w=fmaxf(fmaf(ta0.w,sv.w,hv.w),0.f);
        ta1.x=fmaxf(fmaf(ta1.x,sv.x,hv.x),0.f); ta1.y=fmaxf(fmaf(ta1.y,sv.y,hv.y),0.f);
        ta1.z=fmaxf(fmaf(ta1.z,sv.z,hv.z),0.f); ta1.w=fmaxf(fmaf(ta1.w,sv.w,hv.w),0.f);
        __syncthreads();
        As[lc+0][lr]    = ta0.x; As[lc+1][lr]    = ta0.y; As[lc+2][lr]    = ta0.z; As[lc+3][lr]    = ta0.w;
        As[lc+0][lr+64] = ta1.x; As[lc+1][lr+64] = ta1.y; As[lc+2][lr+64] = ta1.z; As[lc+3][lr+64] = ta1.w;
        Bs[lc+0][lr]    = rb0.x; Bs[lc+1][lr]    = rb0.y; Bs[lc+2][lr]    = rb0.z; Bs[lc+3][lr]    = rb0.w;
        Bs[lc+0][lr+64] = rb1.x; Bs[lc+1][lr+64] = rb1.y; Bs[lc+2][lr+64] = rb1.z; Bs[lc+3][lr+64] = rb1.w;
        __syncthreads();

        if (k0 + 16 < K) {
            ra0 = *(const float4*)(Ap0 + k0 + 16);
            ra1 = *(const float4*)(Ap1 + k0 + 16);
            rb0 = *(const float4*)(Bp0 + k0 + 16);
            rb1 = *(const float4*)(Bp1 + k0 + 16);
        }

        #pragma unroll
        for (int kk = 0; kk < 16; kk++) {
            const ull* bp = (const ull*)&Bs[kk][tx*8];
            ull b2[4];
            #pragma unroll
            for (int j = 0; j < 4; j++) b2[j] = bp[j];
            #pragma unroll
            for (int i = 0; i < 8; i++) {
                float a = As[kk][ty*8 + i];
                ull a2 = pack2(a, a);
                #pragma unroll
                for (int j = 0; j < 4; j++) fma2(acc[i][j], a2, b2[j]);
            }
        }
    }

    #pragma unroll
    for (int i = 0; i < 8; i++) {
        int m = m0 + ty*8 + i;
        #pragma unroll
        for (int j = 0; j < 4; j++) {
            float lo, hi; unpack2(acc[i][j], lo, hi);
            int n = n0 + tx*8 + 2*j;
            C[(size_t)m*N + n]     = lo + bias[n];
            C[(size_t)m*N + n + 1] = hi + bias[n+1];
        }
    }
}

// ---------------- output head ----------------
__global__ void out_kernel(const float* __restrict__ z1,
                           const float* __restrict__ ow,
                           const float* __restrict__ ob,
                           float* __restrict__ y)
{
    const int b = blockIdx.x, t = threadIdx.x;
    float s = 0.f;
    for (int n = t; n < MLPH; n += 256) {
        float h = fmaxf(fmaf(z1[(size_t)b*MLPH + n], g_s2[n], g_t2[n]), 0.f);
        s += h * ow[n];
    }
    __shared__ float sh[256];
    sh[t] = s; __syncthreads();
    for (int st = 128; st > 0; st >>= 1) {
        if (t < st) sh[t] += sh[t+st];
        __syncthreads();
    }
    if (t == 0) y[b] = sh[0] + ob[0];
}

// ---------------- launch ----------------
extern "C" void kernel_launch(void* const* d_in, const int* in_sizes, int n_in,
                              void* d_out, int out_size)
{
    const int*   ids    = (const int*)  d_in[0];
    const float* values = (const float*)d_in[1];
    const float* embt   = (const float*)d_in[2];
    const float* wb     = (const float*)d_in[3];
    const float* query  = (const float*)d_in[4];
    const float* attv   = (const float*)d_in[5];
    const float* bng    = (const float*)d_in[6];
    const float* bnb    = (const float*)d_in[7];
    const float* w0     = (const float*)d_in[8];
    const float* b0     = (const float*)d_in[9];
    const float* gg0    = (const float*)d_in[10];
    const float* be0    = (const float*)d_in[11];
    const float* w1     = (const float*)d_in[12];
    const float* b1     = (const float*)d_in[13];
    const float* gg1    = (const float*)d_in[14];
    const float* be1    = (const float*)d_in[15];
    const float* ow     = (const float*)d_in[16];
    const float* ob     = (const float*)d_in[17];
    float* y = (float*)d_out;

    cudaFuncSetAttribute(embkeys_kernel,
        cudaFuncAttributeMaxDynamicSharedMemorySize, EK_SMEM);
    cudaFuncSetAttribute(gates_gemm,
        cudaFuncAttributeMaxDynamicSharedMemorySize, GG_SMEM);
    cudaFuncSetAttribute(front_v4,
        cudaFuncAttributeMaxDynamicSharedMemorySize, FV_SMEM);
    cudaFuncSetAttribute(gemm0_mma,
        cudaFuncAttributeMaxDynamicSharedMemorySize, G0_SMEM_BYTES);

    float *z0, *z1;
    cudaGetSymbolAddress((void**)&z0, g_z0);
    cudaGetSymbolAddress((void**)&z1, g_z1);

    embkeys_kernel<<<BSZ, 256, EK_SMEM>>>(ids, values, embt, wb);            // 0
    convQ_kernel<<<1, 256>>>(query);                                         // 1
    gates_gemm<<<dim3(NHID/128, MFLAT/128), 256, GG_SMEM>>>();               // 2
    front_v4<<<BSZ, 256, FV_SMEM>>>(attv);                                   // 3 <- profiled
    stats_arm_kernel<<<NHID, 256>>>(bng, bnb);                               // 4
    const int CB_TOTAL = MLPH*KDIM/4/256;
    const int CB1 = 5462, CB2 = 5462, CB3 = CB_TOTAL - CB1 - CB2;
    convB_kernel<<<CB1, 256>>>(w0, 0);                                       // 5
    convB_kernel<<<CB2, 256>>>(w0, CB1);                                     // 6
    convB_kernel<<<CB3, 256>>>(w0, CB1+CB2);                                 // 7
    convA_kernel<<<BSZ*KDIM/4/256, 256>>>();                                 // 8
    gemm0_mma<<<dim3(MLPH/128, BSZ/128), 256, G0_SMEM_BYTES>>>(b0, z0);      // 9
    stats_z_kernel<<<MLPH, 256>>>(z0, gg0, be0, 1);                          // 10
    gemm_bn1<<<dim3(MLPH/128, BSZ/128), 256>>>(z0, w1, b1, z1, BSZ, MLPH, MLPH); // 11
    stats_z_kernel<<<MLPH, 256>>>(z1, gg1, be1, 2);                          // 12
    out_kernel<<<BSZ, 256>>>(z1, ow, ob, y);                                 // 13
}